// round 2
// baseline (speedup 1.0000x reference)
#include <cuda_runtime.h>
#include <math.h>

#define NN    50000      // total nodes
#define NPG   6250       // nodes per graph
#define BG    8          // graphs
#define EE    800000     // total edges
#define CIN   512
#define HH    256
#define HH3   768
#define KSEL  5000
#define RANK_BPG 782     // ceil(6250/8) blocks per graph for rank kernel

// ----------------------------- scratch (static device memory) ---------------
__device__ int   g_is64;
__device__ float g_deg[NN];
__device__ float g_dinv[NN];
__device__ int   g_cnt[NN];
__device__ int   g_rowptr[NN + 1];
__device__ int   g_fill[NN];
__device__ int   g_bsum[64];
__device__ int   g_esrc[EE];
__device__ float g_enorm[EE];
__device__ float g_xw[(size_t)NN * HH];     // 51 MB
__device__ float g_cat[(size_t)NN * HH3];   // 154 MB, [x1|x2|x3]
__device__ float g_score[NN];
__device__ unsigned char g_keep[NN];
__device__ float g_pwn[HH3];
__device__ float g_psum[384 * 256];
__device__ float g_pmax[384 * 256];
__device__ float g_ro[BG * 2 * HH3];

// ----------------------------- dtype probe -----------------------------------
// If edge_index is int64 (node ids < 2^32, nonnegative), every odd 32-bit word
// of the little-endian buffer is 0. If it's int32 (random ids in [0,50000)),
// essentially none of 2048 sampled odd words are all-zero.
__global__ void k_probe(const int* __restrict__ ei32) {
    __shared__ int nz;
    if (threadIdx.x == 0) nz = 0;
    __syncthreads();
    int any = 0;
    for (int i = 1 + 2 * threadIdx.x; i < 4096; i += 2 * blockDim.x)
        if (ei32[i] != 0) any = 1;
    if (any) atomicAdd(&nz, 1);
    __syncthreads();
    if (threadIdx.x == 0) g_is64 = (nz == 0) ? 1 : 0;
}

__device__ __forceinline__ int load_edge(const void* ei, int which, int e) {
    if (g_is64) return (int)((const long long*)ei)[(size_t)which * EE + e];
    return ((const int*)ei)[which * EE + e];
}

// ----------------------------- setup kernels --------------------------------
__global__ void k_init() {
    int i = blockIdx.x * blockDim.x + threadIdx.x;
    if (i < NN) { g_deg[i] = 0.f; g_cnt[i] = 0; g_fill[i] = 0; }
}

__global__ void k_degcnt(const void* __restrict__ ei, const float* __restrict__ ea) {
    int e = blockIdx.x * blockDim.x + threadIdx.x;
    if (e < EE) {
        int d = load_edge(ei, 1, e);
        if ((unsigned)d < NN) {
            atomicAdd(&g_deg[d], ea[e]);
            atomicAdd(&g_cnt[d], 1);
        }
    }
}

__global__ void k_dinv() {
    int i = blockIdx.x * blockDim.x + threadIdx.x;
    if (i < NN) g_dinv[i] = rsqrtf(g_deg[i] + 1.0f);
}

// exclusive scan of g_cnt -> g_rowptr (3 kernels)
__global__ void k_scan1() {
    __shared__ int sm[1024];
    int i = blockIdx.x * 1024 + threadIdx.x;
    int v = (i < NN) ? g_cnt[i] : 0;
    sm[threadIdx.x] = v;
    __syncthreads();
    for (int off = 1; off < 1024; off <<= 1) {
        int t = (threadIdx.x >= off) ? sm[threadIdx.x - off] : 0;
        __syncthreads();
        sm[threadIdx.x] += t;
        __syncthreads();
    }
    if (i < NN) g_rowptr[i] = sm[threadIdx.x] - v;   // exclusive
    if (threadIdx.x == 1023) g_bsum[blockIdx.x] = sm[1023];
}

__global__ void k_scan2() {
    __shared__ int sm[64];
    int t = threadIdx.x;
    int v = (t < 49) ? g_bsum[t] : 0;
    sm[t] = v;
    __syncthreads();
    for (int off = 1; off < 64; off <<= 1) {
        int u = (t >= off) ? sm[t - off] : 0;
        __syncthreads();
        sm[t] += u;
        __syncthreads();
    }
    if (t < 49) g_bsum[t] = sm[t] - v;   // exclusive
}

__global__ void k_scan3() {
    int i = blockIdx.x * blockDim.x + threadIdx.x;
    if (i < NN) g_rowptr[i] += g_bsum[i >> 10];
    if (i == 0) g_rowptr[NN] = EE;
}

__global__ void k_fill(const void* __restrict__ ei, const float* __restrict__ ea) {
    int e = blockIdx.x * blockDim.x + threadIdx.x;
    if (e < EE) {
        int s = load_edge(ei, 0, e);
        int d = load_edge(ei, 1, e);
        if ((unsigned)s < NN && (unsigned)d < NN) {
            int pos = g_rowptr[d] + atomicAdd(&g_fill[d], 1);
            g_esrc[pos]  = s;
            g_enorm[pos] = g_dinv[s] * ea[e] * g_dinv[d];
        }
    }
}

// ----------------------------- SGEMM: C(g_xw) = A[M,Kdim] * B[Kdim,256] -----
__global__ __launch_bounds__(256) void k_gemm(
    const float* __restrict__ Aext, int use_cat, int cat_off,
    int lda, int Kdim, const float* __restrict__ B)
{
    const float* A = use_cat ? (g_cat + cat_off) : Aext;
    __shared__ __align__(16) float As[8][128];
    __shared__ __align__(16) float Bs[8][128];
    int tid  = threadIdx.x;
    int bm   = blockIdx.y, bn = blockIdx.x;
    int arow = tid >> 1, acol = (tid & 1) << 2;
    int brow = tid >> 5, bcol = (tid & 31) << 2;
    int tx   = tid & 15, ty = tid >> 4;

    float acc[8][8];
    #pragma unroll
    for (int i = 0; i < 8; i++)
        #pragma unroll
        for (int j = 0; j < 8; j++) acc[i][j] = 0.f;

    int grow = bm * 128 + arow;
    bool aok = grow < NN;
    const float* Ap = A + (size_t)grow * lda + acol;
    const float* Bp = B + brow * HH + bn * 128 + bcol;

    for (int k0 = 0; k0 < Kdim; k0 += 8) {
        float4 av = aok ? *(const float4*)Ap : make_float4(0.f, 0.f, 0.f, 0.f);
        float4 bv = *(const float4*)Bp;
        As[acol + 0][arow] = av.x;
        As[acol + 1][arow] = av.y;
        As[acol + 2][arow] = av.z;
        As[acol + 3][arow] = av.w;
        *(float4*)&Bs[brow][bcol] = bv;
        __syncthreads();
        #pragma unroll
        for (int k = 0; k < 8; k++) {
            float ar[8], br[8];
            *(float4*)&ar[0] = *(const float4*)&As[k][ty * 8];
            *(float4*)&ar[4] = *(const float4*)&As[k][ty * 8 + 4];
            *(float4*)&br[0] = *(const float4*)&Bs[k][tx * 8];
            *(float4*)&br[4] = *(const float4*)&Bs[k][tx * 8 + 4];
            #pragma unroll
            for (int i = 0; i < 8; i++)
                #pragma unroll
                for (int j = 0; j < 8; j++)
                    acc[i][j] = fmaf(ar[i], br[j], acc[i][j]);
        }
        __syncthreads();
        Ap += 8;
        Bp += 8 * HH;
    }

    #pragma unroll
    for (int i = 0; i < 8; i++) {
        int row = bm * 128 + ty * 8 + i;
        if (row < NN) {
            float* Cp = g_xw + (size_t)row * HH + bn * 128 + tx * 8;
            *(float4*)Cp       = make_float4(acc[i][0], acc[i][1], acc[i][2], acc[i][3]);
            *(float4*)(Cp + 4) = make_float4(acc[i][4], acc[i][5], acc[i][6], acc[i][7]);
        }
    }
}

// ----------------------------- CSR gather-aggregate + bias + relu -----------
// out[n][c] = relu( sum_e norm_e * xw[src_e][c] + dinv[n]^2 * xw[n][c] + b[c] )
__global__ void k_agg(const float* __restrict__ bias, int out_off) {
    int warp = (blockIdx.x * 256 + threadIdx.x) >> 5;
    int lane = threadIdx.x & 31;
    if (warp >= NN) return;
    int n = warp;
    float di = g_dinv[n];
    float d2 = di * di;
    const float* xr = g_xw + (size_t)n * HH;
    float acc[8];
    #pragma unroll
    for (int k = 0; k < 8; k++) acc[k] = d2 * xr[k * 32 + lane];
    int e0 = g_rowptr[n], e1 = g_rowptr[n + 1];
    for (int e = e0; e < e1; e++) {
        int s   = g_esrc[e];
        float w = g_enorm[e];
        const float* sr = g_xw + (size_t)s * HH;
        #pragma unroll
        for (int k = 0; k < 8; k++)
            acc[k] = fmaf(w, sr[k * 32 + lane], acc[k]);
    }
    float* orow = g_cat + (size_t)n * HH3 + out_off;
    #pragma unroll
    for (int k = 0; k < 8; k++)
        orow[k * 32 + lane] = fmaxf(acc[k] + bias[k * 32 + lane], 0.f);
}

// ----------------------------- pooling score --------------------------------
__global__ void k_pwn(const float* __restrict__ pw) {
    __shared__ float red[8];
    __shared__ float s_inv;
    int tid = threadIdx.x;
    float s = 0.f;
    for (int i = tid; i < HH3; i += 256) { float v = pw[i]; s += v * v; }
    #pragma unroll
    for (int o = 16; o; o >>= 1) s += __shfl_xor_sync(0xffffffffu, s, o);
    if ((tid & 31) == 0) red[tid >> 5] = s;
    __syncthreads();
    if (tid == 0) {
        float tot = 0.f;
        for (int i = 0; i < 8; i++) tot += red[i];
        s_inv = rsqrtf(tot);
    }
    __syncthreads();
    for (int i = tid; i < HH3; i += 256) g_pwn[i] = pw[i] * s_inv;
}

__global__ void k_score() {
    int warp = (blockIdx.x * 256 + threadIdx.x) >> 5;
    int lane = threadIdx.x & 31;
    if (warp >= NN) return;
    const float* r = g_cat + (size_t)warp * HH3;
    float s = 0.f;
    #pragma unroll
    for (int k = 0; k < 24; k++)
        s = fmaf(r[k * 32 + lane], g_pwn[k * 32 + lane], s);
    #pragma unroll
    for (int o = 16; o; o >>= 1) s += __shfl_xor_sync(0xffffffffu, s, o);
    if (lane == 0) g_score[warp] = 1.f / (1.f + expf(-s));
}

// exact top-K selection via rank counting (matches jax top_k tie semantics)
__global__ void k_rank() {
    __shared__ float ss[NPG];
    int g  = blockIdx.x / RANK_BPG;
    int bb = blockIdx.x % RANK_BPG;
    for (int i = threadIdx.x; i < NPG; i += 256) ss[i] = g_score[g * NPG + i];
    __syncthreads();
    int wi = threadIdx.x >> 5, lane = threadIdx.x & 31;
    int i = bb * 8 + wi;
    if (i >= NPG) return;
    float si = ss[i];
    int cnt = 0;
    for (int j0 = 0; j0 < NPG; j0 += 32) {
        int j = j0 + lane;
        bool p = false;
        if (j < NPG) {
            float sj = ss[j];
            p = (sj > si) || (sj == si && j < i);
        }
        cnt += __popc(__ballot_sync(0xffffffffu, p));
    }
    if (lane == 0) g_keep[g * NPG + i] = (cnt < KSEL) ? 1 : 0;
}

// ----------------------------- readout (mean + max over selected) -----------
__global__ void k_readout1() {
    int b  = blockIdx.x;        // 0..383 : b = g*48 + cb*16 + ch
    int g  = b / 48;
    int cb = (b / 16) % 3;
    int ch = b % 16;
    int col = cb * 256 + threadIdx.x;
    int i0 = ch * 391, i1 = min(NPG, i0 + 391);
    float sum = 0.f, mx = -3.402823e38f;
    for (int i = i0; i < i1; i++) {
        int n = g * NPG + i;
        if (g_keep[n]) {
            float s = g_score[n];
            float v = s * g_cat[(size_t)n * HH3 + col];
            sum += v;
            mx = fmaxf(mx, v);
        }
    }
    g_psum[b * 256 + threadIdx.x] = sum;
    g_pmax[b * 256 + threadIdx.x] = mx;
}

__global__ void k_readout2() {
    int b = blockIdx.x;         // 0..23
    int g = b / 3, cb = b % 3;
    int col = cb * 256 + threadIdx.x;
    float sum = 0.f, mx = -3.402823e38f;
    for (int ch = 0; ch < 16; ch++) {
        int idx = ((g * 3 + cb) * 16 + ch) * 256 + threadIdx.x;
        sum += g_psum[idx];
        mx = fmaxf(mx, g_pmax[idx]);
    }
    g_ro[g * 2 * HH3 + col]       = sum * (1.0f / KSEL);
    g_ro[g * 2 * HH3 + HH3 + col] = mx;
}

// ----------------------------- MLP head -------------------------------------
__global__ void k_mlp(const float* __restrict__ lw1, const float* __restrict__ lb1,
                      const float* __restrict__ lw2, const float* __restrict__ lb2,
                      const float* __restrict__ lw3, const float* __restrict__ lb3,
                      float* __restrict__ out) {
    __shared__ float ro[2 * HH3];
    __shared__ float h1[HH];
    __shared__ float h2[HH / 2];
    int g = blockIdx.x, tid = threadIdx.x;
    for (int i = tid; i < 2 * HH3; i += 256) ro[i] = g_ro[g * 2 * HH3 + i];
    __syncthreads();
    float a0 = 0.f, a1 = 0.f, a2 = 0.f, a3 = 0.f;
    for (int k = 0; k < 2 * HH3; k += 4) {
        a0 = fmaf(ro[k + 0], lw1[(k + 0) * HH + tid], a0);
        a1 = fmaf(ro[k + 1], lw1[(k + 1) * HH + tid], a1);
        a2 = fmaf(ro[k + 2], lw1[(k + 2) * HH + tid], a2);
        a3 = fmaf(ro[k + 3], lw1[(k + 3) * HH + tid], a3);
    }
    h1[tid] = fmaxf(a0 + a1 + a2 + a3 + lb1[tid], 0.f);
    __syncthreads();
    if (tid < HH / 2) {
        float b0 = 0.f, b1v = 0.f;
        for (int k = 0; k < HH; k += 2) {
            b0  = fmaf(h1[k],     lw2[k * (HH / 2) + tid],       b0);
            b1v = fmaf(h1[k + 1], lw2[(k + 1) * (HH / 2) + tid], b1v);
        }
        h2[tid] = fmaxf(b0 + b1v + lb2[tid], 0.f);
    }
    __syncthreads();
    if (tid < 3) {
        float s = lb3[tid];
        for (int k = 0; k < HH / 2; k++) s = fmaf(h2[k], lw3[k * 3 + tid], s);
        out[g * 3 + tid] = s;
    }
}

// ----------------------------- launch ---------------------------------------
extern "C" void kernel_launch(void* const* d_in, const int* in_sizes, int n_in,
                              void* d_out, int out_size) {
    const float* x   = (const float*)d_in[0];
    const void*  ei  = d_in[1];              // int32 or int64 (probed at runtime)
    const float* ea  = (const float*)d_in[2];
    // d_in[3] = batch (unused): graph id = node / NPG
    const float* W1  = (const float*)d_in[4];
    const float* b1  = (const float*)d_in[5];
    const float* W2  = (const float*)d_in[6];
    const float* b2  = (const float*)d_in[7];
    const float* pw  = (const float*)d_in[8];
    const float* lw1 = (const float*)d_in[9];
    const float* lb1 = (const float*)d_in[10];
    const float* lw2 = (const float*)d_in[11];
    const float* lb2 = (const float*)d_in[12];
    const float* lw3 = (const float*)d_in[13];
    const float* lb3 = (const float*)d_in[14];
    float* out = (float*)d_out;

    // dtype probe + CSR build (shared by all 3 GCN layers)
    k_probe<<<1, 256>>>((const int*)ei);
    k_init<<<(NN + 255) / 256, 256>>>();
    k_degcnt<<<(EE + 255) / 256, 256>>>(ei, ea);
    k_dinv<<<(NN + 255) / 256, 256>>>();
    k_scan1<<<49, 1024>>>();
    k_scan2<<<1, 64>>>();
    k_scan3<<<(NN + 255) / 256, 256>>>();
    k_fill<<<(EE + 255) / 256, 256>>>(ei, ea);

    dim3 ggrid(2, (NN + 127) / 128);
    int aggBlocks = (NN + 7) / 8;

    // layer 1: xw = x @ W1 ; x1 = relu(agg) -> cat[:, 0:256]
    k_gemm<<<ggrid, 256>>>(x, 0, 0, CIN, CIN, W1);
    k_agg<<<aggBlocks, 256>>>(b1, 0);
    // layer 2: xw = x1 @ W2 ; x2 -> cat[:, 256:512]
    k_gemm<<<ggrid, 256>>>(nullptr, 1, 0, HH3, HH, W2);
    k_agg<<<aggBlocks, 256>>>(b2, HH);
    // layer 3: xw = x2 @ W2 ; x3 -> cat[:, 512:768]
    k_gemm<<<ggrid, 256>>>(nullptr, 1, HH, HH3, HH, W2);
    k_agg<<<aggBlocks, 256>>>(b2, 2 * HH);

    // pooling
    k_pwn<<<1, 256>>>(pw);
    k_score<<<(NN + 7) / 8, 256>>>();
    k_rank<<<BG * RANK_BPG, 256>>>();
    k_readout1<<<384, 256>>>();
    k_readout2<<<24, 256>>>();

    // head
    k_mlp<<<BG, 256>>>(lw1, lb1, lw2, lb2, lw3, lb3, out);
}